// round 11
// baseline (speedup 1.0000x reference)
#include <cuda_runtime.h>

#define TT   8
#define NS   512
#define NP   64
#define NTOT 32768   // NS*NP

// Scratch for GAT output -> graph LSTM input ([T, N, 32])
__device__ float g_graph_in[(size_t)TT * NTOT * 32];

typedef unsigned long long u64;

__device__ __forceinline__ u64 ffma2(u64 a, u64 b, u64 c) {
    u64 d;
    asm("fma.rn.f32x2 %0, %1, %2, %3;" : "=l"(d) : "l"(a), "l"(b), "l"(c));
    return d;
}
__device__ __forceinline__ u64 pk2(float lo, float hi) {
    u64 r;
    asm("mov.b64 %0, {%1, %2};" : "=l"(r) : "f"(lo), "f"(hi));
    return r;
}
__device__ __forceinline__ float lo2(u64 v) { return __uint_as_float((unsigned)v); }
__device__ __forceinline__ float hi2(u64 v) { return __uint_as_float((unsigned)(v >> 32)); }

__device__ __forceinline__ float sigmf_(float x) {
    return __fdividef(1.f, 1.f + __expf(-x));
}
__device__ __forceinline__ float tanhf_(float x) {
    float e = __expf(-2.f * fabsf(x));
    float r = __fdividef(1.f - e, 1.f + e);
    return copysignf(r, x);
}

#define BARPAIR(id) asm volatile("bar.sync %0, 64;" :: "r"(id) : "memory")

// ---------------------------------------------------------------------------
// LSTM: 64 peds per 128-thread block. Warps 0,1 compute hidden units 0..15
// (hf=0), warps 2,3 units 16..31 (hf=1). Pair (w, w+2) syncs via a PRIVATE
// named barrier; no block-wide barrier in the time loop, so pairs drift and
// MUFU tails overlap other pairs' FFMA2 phases. Weight LDS is warp-uniform
// broadcast LDS.128. h halves exchanged via double-buffered shared.
// ---------------------------------------------------------------------------
template<int D, bool ENC>
__global__ void __launch_bounds__(128, 4) lstm_kernel(
    const float* __restrict__ xseq,    // [T, N, D]
    const float* __restrict__ h0, const float* __restrict__ c0,   // [N,32]
    const float* __restrict__ Wih,     // [128, D]
    const float* __restrict__ Whh,     // [128, 32]
    const float* __restrict__ bih, const float* __restrict__ bhh, // [128]
    float* __restrict__ hsout,         // [T, N, 32]
    const float* __restrict__ traj_last, // [N,32] (ENC only)
    const float* __restrict__ znoise,    // [S,8]  (ENC only)
    float* __restrict__ enc)             // [N,72] (ENC only)
{
    __shared__ __align__(16) float sWhh[128 * 32];
    __shared__ __align__(16) float sWih[128 * D];
    __shared__ float sB[128];
    __shared__ __align__(16) u64 sH[2][64][17];   // double-buffered h exchange

    const int tid = threadIdx.x;
    for (int i = tid; i < 128 * 32; i += 128) sWhh[i] = Whh[i];
    for (int i = tid; i < 128 * D;  i += 128) sWih[i] = Wih[i];
    sB[tid] = bih[tid] + bhh[tid];
    __syncthreads();

    const int hf    = tid >> 6;          // warp-uniform half select
    const int pl    = tid & 63;          // pedestrian within block
    const int barid = 1 + ((tid >> 5) & 1);
    const int n     = blockIdx.x * 64 + pl;

    float c[16];
    u64 h2[16];                          // full h (32 units) as pairs
    {
        const float4* hv4 = reinterpret_cast<const float4*>(h0 + (size_t)n * 32);
        #pragma unroll
        for (int j = 0; j < 8; j++) {
            float4 hv = hv4[j];
            h2[2*j]   = pk2(hv.x, hv.y);
            h2[2*j+1] = pk2(hv.z, hv.w);
        }
        const float4* cv4 = reinterpret_cast<const float4*>(c0 + (size_t)n * 32 + hf * 16);
        #pragma unroll
        for (int j = 0; j < 4; j++) {
            float4 cv = cv4[j];
            c[4*j] = cv.x; c[4*j+1] = cv.y; c[4*j+2] = cv.z; c[4*j+3] = cv.w;
        }
    }

    #pragma unroll 1
    for (int t = 0; t < TT; t++) {
        float x0 = 0.f, x1 = 0.f, x2 = 0.f;
        u64 xv2[(D == 32) ? 16 : 1];
        if constexpr (D == 3) {
            const float* xp = xseq + ((size_t)t * NTOT + n) * 3;
            x0 = xp[0]; x1 = xp[1]; x2 = xp[2];
        } else {
            const float4* xp4 = reinterpret_cast<const float4*>(xseq + ((size_t)t * NTOT + n) * 32);
            #pragma unroll
            for (int j = 0; j < 8; j++) {
                float4 v = xp4[j];
                xv2[2*j]   = pk2(v.x, v.y);
                xv2[2*j+1] = pk2(v.z, v.w);
            }
        }

        float* op = hsout + ((size_t)t * NTOT + n) * 32 + hf * 16;
        u64 hn[8];                       // my 16 new h values as pairs

        #pragma unroll 1
        for (int kp8 = 0; kp8 < 8; kp8++) {
            const int k0 = hf * 16 + 2 * kp8;   // warp-uniform row index
            const int k1 = k0 + 1;
            u64 ai0 = 0, af0 = 0, ag0 = 0, ao0 = 0;
            u64 ai1 = 0, af1 = 0, ag1 = 0, ao1 = 0;
            #pragma unroll
            for (int j = 0; j < 8; j++) {
                const u64 va = h2[2*j], vb = h2[2*j+1];
                ulonglong2 w;
                w = *(const ulonglong2*)(sWhh + (k0      ) * 32 + 4*j); ai0 = ffma2(w.x, va, ai0); ai0 = ffma2(w.y, vb, ai0);
                w = *(const ulonglong2*)(sWhh + (k0 + 32 ) * 32 + 4*j); af0 = ffma2(w.x, va, af0); af0 = ffma2(w.y, vb, af0);
                w = *(const ulonglong2*)(sWhh + (k0 + 64 ) * 32 + 4*j); ag0 = ffma2(w.x, va, ag0); ag0 = ffma2(w.y, vb, ag0);
                w = *(const ulonglong2*)(sWhh + (k0 + 96 ) * 32 + 4*j); ao0 = ffma2(w.x, va, ao0); ao0 = ffma2(w.y, vb, ao0);
                w = *(const ulonglong2*)(sWhh + (k1      ) * 32 + 4*j); ai1 = ffma2(w.x, va, ai1); ai1 = ffma2(w.y, vb, ai1);
                w = *(const ulonglong2*)(sWhh + (k1 + 32 ) * 32 + 4*j); af1 = ffma2(w.x, va, af1); af1 = ffma2(w.y, vb, af1);
                w = *(const ulonglong2*)(sWhh + (k1 + 64 ) * 32 + 4*j); ag1 = ffma2(w.x, va, ag1); ag1 = ffma2(w.y, vb, ag1);
                w = *(const ulonglong2*)(sWhh + (k1 + 96 ) * 32 + 4*j); ao1 = ffma2(w.x, va, ao1); ao1 = ffma2(w.y, vb, ao1);
            }
            if constexpr (D == 32) {
                #pragma unroll
                for (int j = 0; j < 8; j++) {
                    const u64 va = xv2[2*j], vb = xv2[2*j+1];
                    ulonglong2 w;
                    w = *(const ulonglong2*)(sWih + (k0      ) * 32 + 4*j); ai0 = ffma2(w.x, va, ai0); ai0 = ffma2(w.y, vb, ai0);
                    w = *(const ulonglong2*)(sWih + (k0 + 32 ) * 32 + 4*j); af0 = ffma2(w.x, va, af0); af0 = ffma2(w.y, vb, af0);
                    w = *(const ulonglong2*)(sWih + (k0 + 64 ) * 32 + 4*j); ag0 = ffma2(w.x, va, ag0); ag0 = ffma2(w.y, vb, ag0);
                    w = *(const ulonglong2*)(sWih + (k0 + 96 ) * 32 + 4*j); ao0 = ffma2(w.x, va, ao0); ao0 = ffma2(w.y, vb, ao0);
                    w = *(const ulonglong2*)(sWih + (k1      ) * 32 + 4*j); ai1 = ffma2(w.x, va, ai1); ai1 = ffma2(w.y, vb, ai1);
                    w = *(const ulonglong2*)(sWih + (k1 + 32 ) * 32 + 4*j); af1 = ffma2(w.x, va, af1); af1 = ffma2(w.y, vb, af1);
                    w = *(const ulonglong2*)(sWih + (k1 + 64 ) * 32 + 4*j); ag1 = ffma2(w.x, va, ag1); ag1 = ffma2(w.y, vb, ag1);
                    w = *(const ulonglong2*)(sWih + (k1 + 96 ) * 32 + 4*j); ao1 = ffma2(w.x, va, ao1); ao1 = ffma2(w.y, vb, ao1);
                }
            }
            float gi0 = lo2(ai0) + hi2(ai0) + sB[k0];
            float gf0 = lo2(af0) + hi2(af0) + sB[32 + k0];
            float gg0 = lo2(ag0) + hi2(ag0) + sB[64 + k0];
            float go0 = lo2(ao0) + hi2(ao0) + sB[96 + k0];
            float gi1 = lo2(ai1) + hi2(ai1) + sB[k1];
            float gf1 = lo2(af1) + hi2(af1) + sB[32 + k1];
            float gg1 = lo2(ag1) + hi2(ag1) + sB[64 + k1];
            float go1 = lo2(ao1) + hi2(ao1) + sB[96 + k1];
            if constexpr (D == 3) {
                gi0 += sWih[(k0      )*3]*x0 + sWih[(k0      )*3+1]*x1 + sWih[(k0      )*3+2]*x2;
                gf0 += sWih[(k0 + 32 )*3]*x0 + sWih[(k0 + 32 )*3+1]*x1 + sWih[(k0 + 32 )*3+2]*x2;
                gg0 += sWih[(k0 + 64 )*3]*x0 + sWih[(k0 + 64 )*3+1]*x1 + sWih[(k0 + 64 )*3+2]*x2;
                go0 += sWih[(k0 + 96 )*3]*x0 + sWih[(k0 + 96 )*3+1]*x1 + sWih[(k0 + 96 )*3+2]*x2;
                gi1 += sWih[(k1      )*3]*x0 + sWih[(k1      )*3+1]*x1 + sWih[(k1      )*3+2]*x2;
                gf1 += sWih[(k1 + 32 )*3]*x0 + sWih[(k1 + 32 )*3+1]*x1 + sWih[(k1 + 32 )*3+2]*x2;
                gg1 += sWih[(k1 + 64 )*3]*x0 + sWih[(k1 + 64 )*3+1]*x1 + sWih[(k1 + 64 )*3+2]*x2;
                go1 += sWih[(k1 + 96 )*3]*x0 + sWih[(k1 + 96 )*3+1]*x1 + sWih[(k1 + 96 )*3+2]*x2;
            }
            const int kc0 = 2 * kp8, kc1 = kc0 + 1;
            float c0n = sigmf_(gf0) * c[kc0] + sigmf_(gi0) * tanhf_(gg0);
            float c1n = sigmf_(gf1) * c[kc1] + sigmf_(gi1) * tanhf_(gg1);
            c[kc0] = c0n; c[kc1] = c1n;
            float h0v = sigmf_(go0) * tanhf_(c0n);
            float h1v = sigmf_(go1) * tanhf_(c1n);
            hn[kp8] = pk2(h0v, h1v);
        }

        // write my half of h to gmem (4x float4)
        #pragma unroll
        for (int j = 0; j < 4; j++)
            reinterpret_cast<float4*>(op)[j] =
                make_float4(lo2(hn[2*j]), hi2(hn[2*j]), lo2(hn[2*j+1]), hi2(hn[2*j+1]));

        // exchange halves with partner warp (double-buffered, 1 named barrier)
        u64* row = &sH[t & 1][pl][0];
        #pragma unroll
        for (int j = 0; j < 8; j++) row[hf * 8 + j] = hn[j];
        BARPAIR(barid);
        #pragma unroll
        for (int j = 0; j < 8; j++) {
            h2[hf * 8 + j]       = hn[j];
            h2[(1 - hf) * 8 + j] = row[(1 - hf) * 8 + j];
        }

        if (ENC && t == TT - 1) {
            float* ep = enc + (size_t)n * 72;
            const float4* tl = reinterpret_cast<const float4*>(traj_last + (size_t)n * 32 + hf * 16);
            #pragma unroll
            for (int j = 0; j < 4; j++)
                reinterpret_cast<float4*>(ep + hf * 16)[j] = tl[j];
            #pragma unroll
            for (int j = 0; j < 4; j++)
                reinterpret_cast<float4*>(ep + 32 + hf * 16)[j] =
                    make_float4(lo2(hn[2*j]), hi2(hn[2*j]), lo2(hn[2*j+1]), hi2(hn[2*j+1]));
            if (hf) {
                const float4* zp = reinterpret_cast<const float4*>(znoise + (size_t)(n >> 6) * 8);
                reinterpret_cast<float4*>(ep + 64)[0] = zp[0];
                reinterpret_cast<float4*>(ep + 64)[1] = zp[1];
            }
        }
    }
}

// ---------------------------------------------------------------------------
// GAT encoder: one block per (scene, t). 256 threads, 72.6 KB smem, 3 blk/SM.
// ---------------------------------------------------------------------------
#define GAT_SMEM_FLOATS 18160
#define GAT_SMEM_BYTES  (GAT_SMEM_FLOATS * 4)

__global__ void __launch_bounds__(256, 3) gat_kernel(
    const float* __restrict__ trajhs,   // [T, N, 32]
    const float* __restrict__ w0,       // [4,32,16]
    const float* __restrict__ asrc0, const float* __restrict__ adst0,  // [4,16]
    const float* __restrict__ bias0,    // [16]
    const float* __restrict__ w1,       // [1,64,32]
    const float* __restrict__ asrc1, const float* __restrict__ adst1,  // [32]
    const float* __restrict__ bias1,    // [32]
    float* __restrict__ gout)           // [T, N, 32]
{
    extern __shared__ __align__(16) float sm[];
    float* XN  = sm;           // 64 x 33           (dead after hp0)
    float* W0S = sm + 2112;    // 32 x 64           (dead after hp0)
    float* EM  = sm;           // 64 x 65           (overlays XN+W0S)
    float* HP0 = sm + 4160;    // 64 x 68
    float* S0  = sm + 8512;    // 4 x 64
    float* D0  = sm + 8768;    // 4 x 64
    float* X1  = sm + 9024;    // 64 x 68
    float* W1S = sm + 13376;   // 64 x 32
    float* HP1 = sm + 15424;   // 64 x 36
    float* S1  = sm + 17728;   // 64
    float* D1  = sm + 17792;   // 64
    float* ES  = sm + 17856;   // 64
    float* A0S = sm + 17920;   // 64
    float* A0D = sm + 17984;   // 64
    float* A1S = sm + 18048;   // 32
    float* A1D = sm + 18080;   // 32
    float* B0  = sm + 18112;   // 16
    float* B1  = sm + 18128;   // 32

    const int tid = threadIdx.x;
    const int b = blockIdx.x;
    const int s = b >> 3, t = b & 7;

    const float* src = trajhs + ((size_t)t * NTOT + s * 64) * 32;
    for (int i = tid; i < 2048; i += 256) XN[(i >> 5) * 33 + (i & 31)] = src[i];
    for (int i = tid; i < 2048; i += 256) {
        int f = i >> 6, cc = i & 63;
        W0S[i] = w0[((cc >> 4) << 9) + (f << 4) + (cc & 15)];
    }
    for (int i = tid; i < 2048; i += 256) W1S[i] = w1[i];
    if (tid < 64)       { A0S[tid] = asrc0[tid]; A0D[tid] = adst0[tid]; }
    else if (tid < 96)  { A1S[tid - 64] = asrc1[tid - 64]; A1D[tid - 64] = adst1[tid - 64]; }
    else if (tid < 112) { B0[tid - 96] = bias0[tid - 96]; }
    else if (tid < 144) { B1[tid - 112] = bias1[tid - 112]; }
    __syncthreads();

    // --- instance norm 0: 32 features x 64 peds, 8 threads per feature ---
    {
        const int f = tid >> 3, g = tid & 7;
        float mval = 0.f;
        #pragma unroll
        for (int i = 0; i < 8; i++) mval += XN[(g + 8 * i) * 33 + f];
        mval += __shfl_xor_sync(0xFFFFFFFFu, mval, 1);
        mval += __shfl_xor_sync(0xFFFFFFFFu, mval, 2);
        mval += __shfl_xor_sync(0xFFFFFFFFu, mval, 4);
        const float m = mval * 0.015625f;
        float v = 0.f;
        #pragma unroll
        for (int i = 0; i < 8; i++) { float d = XN[(g + 8 * i) * 33 + f] - m; v = fmaf(d, d, v); }
        v += __shfl_xor_sync(0xFFFFFFFFu, v, 1);
        v += __shfl_xor_sync(0xFFFFFFFFu, v, 2);
        v += __shfl_xor_sync(0xFFFFFFFFu, v, 4);
        const float inv = rsqrtf(fmaf(v, 0.015625f, 1e-5f));
        #pragma unroll
        for (int i = 0; i < 8; i++) {
            const int idx = (g + 8 * i) * 33 + f;
            XN[idx] = (XN[idx] - m) * inv;
        }
    }
    __syncthreads();

    // --- hp0 = xn @ w0 : [64x32] @ [32x64] ---
    {
        const int p  = tid >> 2;
        const int cb = (tid & 3) << 4;
        u64 acc[8] = {0, 0, 0, 0, 0, 0, 0, 0};
        #pragma unroll
        for (int f = 0; f < 32; f++) {
            float xv = XN[p * 33 + f];
            u64 xx = pk2(xv, xv);
            const ulonglong2* w = reinterpret_cast<const ulonglong2*>(W0S + f * 64 + cb);
            #pragma unroll
            for (int j = 0; j < 4; j++) {
                ulonglong2 ww = w[j];
                acc[2*j]   = ffma2(ww.x, xx, acc[2*j]);
                acc[2*j+1] = ffma2(ww.y, xx, acc[2*j+1]);
            }
        }
        u64* dst = reinterpret_cast<u64*>(HP0 + p * 68 + cb);
        #pragma unroll
        for (int j = 0; j < 8; j++) dst[j] = acc[j];
    }
    __syncthreads();

    // --- s0, d0 ---
    {
        const int h = tid >> 6, p = tid & 63;
        const float* hb = HP0 + p * 68 + h * 16;
        const float* as = A0S + h * 16;
        const float* ad = A0D + h * 16;
        float sv = 0.f, dv = 0.f;
        #pragma unroll
        for (int o = 0; o < 16; o++) {
            float hv = hb[o];
            sv = fmaf(hv, as[o], sv);
            dv = fmaf(hv, ad[o], dv);
        }
        S0[h * 64 + p] = sv;
        D0[h * 64 + p] = dv;
    }
    __syncthreads();

    // --- attention0: softmax over q, apply to hp0, +bias, elu -> X1 ---
    {
        const int h = tid >> 6, p = tid & 63;
        const float sp = S0[h * 64 + p];
        const float* dd = D0 + h * 64;
        float mx = -3.4e38f;
        #pragma unroll 8
        for (int q = 0; q < 64; q++) {
            float e = sp + dd[q];
            e = e > 0.f ? e : 0.2f * e;
            mx = fmaxf(mx, e);
        }
        u64 acc[8] = {0, 0, 0, 0, 0, 0, 0, 0};
        float den = 0.f;
        #pragma unroll 2
        for (int q = 0; q < 64; q++) {
            float e = sp + dd[q];
            e = e > 0.f ? e : 0.2f * e;
            float w = __expf(e - mx);
            den += w;
            u64 ww = pk2(w, w);
            const ulonglong2* hq = reinterpret_cast<const ulonglong2*>(HP0 + q * 68 + h * 16);
            #pragma unroll
            for (int j = 0; j < 4; j++) {
                ulonglong2 hv = hq[j];
                acc[2*j]   = ffma2(hv.x, ww, acc[2*j]);
                acc[2*j+1] = ffma2(hv.y, ww, acc[2*j+1]);
            }
        }
        float inv = __fdividef(1.f, den);
        float* xo = X1 + p * 68 + h * 16;
        #pragma unroll
        for (int j = 0; j < 8; j++) {
            float v0 = fmaf(lo2(acc[j]), inv, B0[2 * j]);
            float v1 = fmaf(hi2(acc[j]), inv, B0[2 * j + 1]);
            v0 = v0 > 0.f ? v0 : expm1f(v0);
            v1 = v1 > 0.f ? v1 : expm1f(v1);
            xo[2 * j] = v0;
            xo[2 * j + 1] = v1;
        }
    }
    __syncthreads();

    // --- instance norm 1: 64 features x 64 peds, 4 threads per feature ---
    {
        const int f = tid >> 2, g = tid & 3;
        float mval = 0.f;
        #pragma unroll
        for (int i = 0; i < 16; i++) mval += X1[(g + 4 * i) * 68 + f];
        mval += __shfl_xor_sync(0xFFFFFFFFu, mval, 1);
        mval += __shfl_xor_sync(0xFFFFFFFFu, mval, 2);
        const float m = mval * 0.015625f;
        float v = 0.f;
        #pragma unroll
        for (int i = 0; i < 16; i++) { float d = X1[(g + 4 * i) * 68 + f] - m; v = fmaf(d, d, v); }
        v += __shfl_xor_sync(0xFFFFFFFFu, v, 1);
        v += __shfl_xor_sync(0xFFFFFFFFu, v, 2);
        const float inv = rsqrtf(fmaf(v, 0.015625f, 1e-5f));
        #pragma unroll
        for (int i = 0; i < 16; i++) {
            const int idx = (g + 4 * i) * 68 + f;
            X1[idx] = (X1[idx] - m) * inv;
        }
    }
    __syncthreads();

    // --- hp1 = x1 @ w1 : [64x64] @ [64x32] ---
    {
        const int p  = tid >> 2;
        const int ob = (tid & 3) << 3;
        u64 acc[4] = {0, 0, 0, 0};
        #pragma unroll
        for (int f = 0; f < 64; f++) {
            float xv = X1[p * 68 + f];
            u64 xx = pk2(xv, xv);
            const ulonglong2* w = reinterpret_cast<const ulonglong2*>(W1S + f * 32 + ob);
            #pragma unroll
            for (int j = 0; j < 2; j++) {
                ulonglong2 ww = w[j];
                acc[2*j]   = ffma2(ww.x, xx, acc[2*j]);
                acc[2*j+1] = ffma2(ww.y, xx, acc[2*j+1]);
            }
        }
        u64* dst = reinterpret_cast<u64*>(HP1 + p * 36 + ob);
        #pragma unroll
        for (int j = 0; j < 4; j++) dst[j] = acc[j];
    }
    __syncthreads();

    // --- s1, d1 (128 threads) ---
    if (tid < 128) {
        const int p = tid & 63;
        const bool ds = tid >= 64;
        const float* a = ds ? A1D : A1S;
        const float* hb = HP1 + p * 36;
        float sv = 0.f;
        #pragma unroll
        for (int o = 0; o < 32; o++) sv = fmaf(hb[o], a[o], sv);
        (ds ? D1 : S1)[p] = sv;
    }
    __syncthreads();

    // --- softmax weights for layer 1 (4 threads per row) ---
    {
        const int p = tid >> 2, qh = tid & 3;
        const float sp = S1[p];
        float mx = -3.4e38f;
        #pragma unroll
        for (int qi = 0; qi < 16; qi++) {
            float e = sp + D1[qh * 16 + qi];
            e = e > 0.f ? e : 0.2f * e;
            mx = fmaxf(mx, e);
        }
        mx = fmaxf(mx, __shfl_xor_sync(0xFFFFFFFFu, mx, 1));
        mx = fmaxf(mx, __shfl_xor_sync(0xFFFFFFFFu, mx, 2));
        float den = 0.f;
        #pragma unroll
        for (int qi = 0; qi < 16; qi++) {
            const int q = qh * 16 + qi;
            float e = sp + D1[q];
            e = e > 0.f ? e : 0.2f * e;
            float w = __expf(e - mx);
            EM[p * 65 + q] = w;
            den += w;
        }
        den += __shfl_xor_sync(0xFFFFFFFFu, den, 1);
        den += __shfl_xor_sync(0xFFFFFFFFu, den, 2);
        if (qh == 0) ES[p] = __fdividef(1.f, den);
    }
    __syncthreads();

    // --- apply attn1, +bias, write graph_in ---
    {
        const int p  = tid >> 2;
        const int ob = (tid & 3) << 3;
        u64 acc[4] = {0, 0, 0, 0};
        const float* ew = EM + p * 65;
        #pragma unroll 2
        for (int q = 0; q < 64; q++) {
            float w = ew[q];
            u64 ww = pk2(w, w);
            const ulonglong2* hq = reinterpret_cast<const ulonglong2*>(HP1 + q * 36 + ob);
            #pragma unroll
            for (int j = 0; j < 2; j++) {
                ulonglong2 hv = hq[j];
                acc[2*j]   = ffma2(hv.x, ww, acc[2*j]);
                acc[2*j+1] = ffma2(hv.y, ww, acc[2*j+1]);
            }
        }
        float inv = ES[p];
        float2* gp = reinterpret_cast<float2*>(
            gout + ((size_t)t * NTOT + s * 64 + p) * 32 + ob);
        #pragma unroll
        for (int j = 0; j < 4; j++) {
            float v0 = fmaf(lo2(acc[j]), inv, B1[ob + 2 * j]);
            float v1 = fmaf(hi2(acc[j]), inv, B1[ob + 2 * j + 1]);
            gp[j] = make_float2(v0, v1);
        }
    }
}

// ---------------------------------------------------------------------------
extern "C" void kernel_launch(void* const* d_in, const int* in_sizes, int n_in,
                              void* d_out, int out_size)
{
    (void)in_sizes; (void)n_in; (void)out_size;
    const float* obs  = (const float*)d_in[0];
    const float* h0t  = (const float*)d_in[1];
    const float* c0t  = (const float*)d_in[2];
    const float* h0g  = (const float*)d_in[3];
    const float* c0g  = (const float*)d_in[4];
    const float* zn   = (const float*)d_in[5];
    const float* WihT = (const float*)d_in[6];
    const float* WhhT = (const float*)d_in[7];
    const float* bihT = (const float*)d_in[8];
    const float* bhhT = (const float*)d_in[9];
    const float* WihG = (const float*)d_in[10];
    const float* WhhG = (const float*)d_in[11];
    const float* bihG = (const float*)d_in[12];
    const float* bhhG = (const float*)d_in[13];
    const float* w0   = (const float*)d_in[14];
    const float* as0  = (const float*)d_in[15];
    const float* ad0  = (const float*)d_in[16];
    const float* b0   = (const float*)d_in[17];
    const float* w1   = (const float*)d_in[18];
    const float* as1  = (const float*)d_in[19];
    const float* ad1  = (const float*)d_in[20];
    const float* b1   = (const float*)d_in[21];

    float* out = (float*)d_out;
    float* enc = out;                                  // [N,72]
    float* ghs = out + (size_t)NTOT * 72;              // [T,N,32]
    float* ths = ghs + (size_t)TT * NTOT * 32;         // [T,N,32]

    float* gin = nullptr;
    cudaGetSymbolAddress((void**)&gin, g_graph_in);

    // 1) traj LSTM -> traj_hs (directly into output region)
    lstm_kernel<3, false><<<NTOT / 64, 128>>>(
        obs, h0t, c0t, WihT, WhhT, bihT, bhhT, ths, nullptr, nullptr, nullptr);

    // 2) GAT encoder -> graph_in scratch
    cudaFuncSetAttribute(gat_kernel,
                         cudaFuncAttributeMaxDynamicSharedMemorySize, GAT_SMEM_BYTES);
    gat_kernel<<<NS * TT, 256, GAT_SMEM_BYTES>>>(
        ths, w0, as0, ad0, b0, w1, as1, ad1, b1, gin);

    // 3) graph LSTM -> graph_hs + encoded (traj_hs[-1] | graph_hs[-1] | noise)
    lstm_kernel<32, true><<<NTOT / 64, 128>>>(
        gin, h0g, c0g, WihG, WhhG, bihG, bhhG, ghs,
        ths + (size_t)(TT - 1) * NTOT * 32, zn, enc);
}

// round 12
// speedup vs baseline: 1.8720x; 1.8720x over previous
#include <cuda_runtime.h>

#define TT   8
#define NS   512
#define NTOT 32768   // NS*NP

// Scratch for GAT output -> graph LSTM input ([T, N, 32])
__device__ float g_graph_in[(size_t)TT * NTOT * 32];

typedef unsigned long long u64;
typedef unsigned int u32;

__device__ __forceinline__ u64 ffma2(u64 a, u64 b, u64 c) {
    u64 d;
    asm("fma.rn.f32x2 %0, %1, %2, %3;" : "=l"(d) : "l"(a), "l"(b), "l"(c));
    return d;
}
__device__ __forceinline__ u64 pk2(float lo, float hi) {
    u64 r;
    asm("mov.b64 %0, {%1, %2};" : "=l"(r) : "f"(lo), "f"(hi));
    return r;
}
__device__ __forceinline__ float lo2(u64 v) { return __uint_as_float((unsigned)v); }
__device__ __forceinline__ float hi2(u64 v) { return __uint_as_float((unsigned)(v >> 32)); }

__device__ __forceinline__ float sigmf_(float x) {
    return __fdividef(1.f, 1.f + __expf(-x));
}
__device__ __forceinline__ float tanhf_(float x) {
    float e = __expf(-2.f * fabsf(x));
    float r = __fdividef(1.f - e, 1.f + e);
    return copysignf(r, x);
}

// ---------------------------------------------------------------------------
// LSTM as per-step tiled GEMM. Block = 64 peds, 256 threads:
//   thread (k = lane 0..31, pg = warp 0..7) computes gates i/f/g/o of hidden
//   unit k for 8 peds (pg*8..pg*8+7) -> 16 independent FFMA2 chains.
// Weights duplicated as (w,w) u64 pairs in smem, row stride 34 u64 so
// per-lane LDS.128 is bank-conflict-free (bank pattern 4k..4k+3 per 8-lane
// phase). h tile double-buffered in smem (broadcast LDS.128 reads);
// ONE __syncthreads per time step. c state in registers (8 floats/thread).
// ---------------------------------------------------------------------------
template<int D, bool ENC>
__global__ void __launch_bounds__(256, 2) lstm_kernel(
    const float* __restrict__ xseq,    // [T, N, D]
    const float* __restrict__ h0, const float* __restrict__ c0,   // [N,32]
    const float* __restrict__ Wih,     // [128, D]
    const float* __restrict__ Whh,     // [128, 32]
    const float* __restrict__ bih, const float* __restrict__ bhh, // [128]
    float* __restrict__ hsout,         // [T, N, 32]
    const float* __restrict__ traj_last, // [N,32] (ENC only)
    const float* __restrict__ znoise,    // [S,8]  (ENC only)
    float* __restrict__ enc)             // [N,72] (ENC only)
{
    constexpr int SWH   = 34;                    // u64 row stride, h weights
    constexpr int SWX   = (D == 3) ? 5 : 34;     // u64 row stride, x weights
    constexpr int WDH_SZ = 128 * SWH;            // 4352 u64
    constexpr int WDX_SZ = 128 * SWX;
    constexpr int HB_SZ  = 2 * 32 * 34;          // double-buffered h tile
    constexpr int HSTRIDE = 32 * 34;

    extern __shared__ __align__(16) u64 smU[];
    u64* WDH = smU;                  // [128][34] (w,w) pairs
    u64* WDX = WDH + WDH_SZ;         // [128][SWX]
    u64* HB  = WDX + WDX_SZ;         // [2][32][34] ped-pairs
    u64* XB  = HB + HB_SZ;           // D=3: [8][3][34]; D=32: [2][32][34]

    const int tid  = threadIdx.x;
    const int k    = tid & 31;
    const int pg   = tid >> 5;
    const int pg4  = pg * 4;
    const int base = blockIdx.x * 64;

    // ---- stage duplicated weights ----
    for (int i = tid; i < 128 * 32; i += 256) {
        int r = i >> 5, f = i & 31;
        float w = Whh[r * 32 + f];
        WDH[r * SWH + f] = pk2(w, w);
    }
    if constexpr (D == 3) {
        for (int i = tid; i < 128 * 3; i += 256) {
            int r = i / 3, f = i - r * 3;
            float w = Wih[r * 3 + f];
            WDX[r * SWX + f] = pk2(w, w);
        }
    } else {
        for (int i = tid; i < 128 * 32; i += 256) {
            int r = i >> 5, f = i & 31;
            float w = Wih[r * 32 + f];
            WDX[r * SWX + f] = pk2(w, w);
        }
    }

    // biases for my unit k (lane-distinct coalesced LDG)
    const float bI = bih[k]      + bhh[k];
    const float bF = bih[32 + k] + bhh[32 + k];
    const float bG = bih[64 + k] + bhh[64 + k];
    const float bO = bih[96 + k] + bhh[96 + k];

    // ---- c init + h0 stage into Hbuf[0] ----
    float c[8];
    {
        float hv0[8];
        #pragma unroll
        for (int j = 0; j < 8; j++) {
            c[j]   = c0[(size_t)(base + pg * 8 + j) * 32 + k];
            hv0[j] = h0[(size_t)(base + pg * 8 + j) * 32 + k];
        }
        u64* HN = HB + (size_t)k * 34 + pg4;
        #pragma unroll
        for (int jj = 0; jj < 4; jj++) HN[jj] = pk2(hv0[2*jj], hv0[2*jj+1]);
    }

    // ---- x staging ----
    const int xpp = tid >> 2;            // D=32 staging: ped
    const int xpo = (tid & 3) << 3;      // D=32 staging: feature offset
    if constexpr (D == 3) {
        // stage ALL 8 steps once: XB[t][xf][pair halves]
        u32* XH = reinterpret_cast<u32*>(XB);
        for (int i = tid; i < 8 * 64 * 3; i += 256) {
            int tt  = i / 192;
            int rem = i - tt * 192;
            int p   = rem / 3;
            int xf  = rem - p * 3;
            float xv = xseq[((size_t)tt * NTOT + base + p) * 3 + xf];
            XH[2 * ((tt * 3 + xf) * 34 + (p >> 1)) + (p & 1)] = __float_as_uint(xv);
        }
    } else {
        // stage t=0 into XB buf 0
        const float4* xp = reinterpret_cast<const float4*>(
            xseq + ((size_t)base + xpp) * 32 + xpo);
        float4 A = xp[0], Bq = xp[1];
        float av[8] = {A.x, A.y, A.z, A.w, Bq.x, Bq.y, Bq.z, Bq.w};
        u32* XH = reinterpret_cast<u32*>(XB);
        #pragma unroll
        for (int e = 0; e < 8; e++)
            XH[2 * ((xpo + e) * 34 + (xpp >> 1)) + (xpp & 1)] = __float_as_uint(av[e]);
    }
    __syncthreads();

    const int kb0 = (0 * 32 + k) * SWH;
    const int kb1 = (1 * 32 + k) * SWH;
    const int kb2 = (2 * 32 + k) * SWH;
    const int kb3 = (3 * 32 + k) * SWH;
    const int xb0 = (0 * 32 + k) * SWX;
    const int xb1 = (1 * 32 + k) * SWX;
    const int xb2 = (2 * 32 + k) * SWX;
    const int xb3 = (3 * 32 + k) * SWX;

    #pragma unroll 1
    for (int t = 0; t < TT; t++) {
        u64 aI[4] = {0,0,0,0}, aF[4] = {0,0,0,0}, aG[4] = {0,0,0,0}, aO[4] = {0,0,0,0};

        // ---- h GEMM: 32 features ----
        const u64* HT = HB + (t & 1) * HSTRIDE;
        #pragma unroll
        for (int fo = 0; fo < 8; fo++) {
            const int f4 = fo * 4;
            u64 wv[4][4];   // [gate][f']
            {
                ulonglong2 q;
                q = *(const ulonglong2*)&WDH[kb0 + f4];     wv[0][0] = q.x; wv[0][1] = q.y;
                q = *(const ulonglong2*)&WDH[kb0 + f4 + 2]; wv[0][2] = q.x; wv[0][3] = q.y;
                q = *(const ulonglong2*)&WDH[kb1 + f4];     wv[1][0] = q.x; wv[1][1] = q.y;
                q = *(const ulonglong2*)&WDH[kb1 + f4 + 2]; wv[1][2] = q.x; wv[1][3] = q.y;
                q = *(const ulonglong2*)&WDH[kb2 + f4];     wv[2][0] = q.x; wv[2][1] = q.y;
                q = *(const ulonglong2*)&WDH[kb2 + f4 + 2]; wv[2][2] = q.x; wv[2][3] = q.y;
                q = *(const ulonglong2*)&WDH[kb3 + f4];     wv[3][0] = q.x; wv[3][1] = q.y;
                q = *(const ulonglong2*)&WDH[kb3 + f4 + 2]; wv[3][2] = q.x; wv[3][3] = q.y;
            }
            u64 hv[4][4];   // [f'][pedpair]  (broadcast loads)
            #pragma unroll
            for (int fp = 0; fp < 4; fp++) {
                ulonglong2 q0 = *(const ulonglong2*)&HT[(f4 + fp) * 34 + pg4];
                ulonglong2 q1 = *(const ulonglong2*)&HT[(f4 + fp) * 34 + pg4 + 2];
                hv[fp][0] = q0.x; hv[fp][1] = q0.y; hv[fp][2] = q1.x; hv[fp][3] = q1.y;
            }
            #pragma unroll
            for (int fp = 0; fp < 4; fp++) {
                #pragma unroll
                for (int pp = 0; pp < 4; pp++) {
                    aI[pp] = ffma2(wv[0][fp], hv[fp][pp], aI[pp]);
                    aF[pp] = ffma2(wv[1][fp], hv[fp][pp], aF[pp]);
                    aG[pp] = ffma2(wv[2][fp], hv[fp][pp], aG[pp]);
                    aO[pp] = ffma2(wv[3][fp], hv[fp][pp], aO[pp]);
                }
            }
        }

        // ---- x GEMM ----
        if constexpr (D == 3) {
            const u64* XT = XB + (size_t)t * (3 * 34);
            #pragma unroll
            for (int xf = 0; xf < 3; xf++) {
                u64 wI = WDX[xb0 + xf], wF = WDX[xb1 + xf];
                u64 wG = WDX[xb2 + xf], wO = WDX[xb3 + xf];
                ulonglong2 q0 = *(const ulonglong2*)&XT[xf * 34 + pg4];
                ulonglong2 q1 = *(const ulonglong2*)&XT[xf * 34 + pg4 + 2];
                u64 xv[4] = {q0.x, q0.y, q1.x, q1.y};
                #pragma unroll
                for (int pp = 0; pp < 4; pp++) {
                    aI[pp] = ffma2(wI, xv[pp], aI[pp]);
                    aF[pp] = ffma2(wF, xv[pp], aF[pp]);
                    aG[pp] = ffma2(wG, xv[pp], aG[pp]);
                    aO[pp] = ffma2(wO, xv[pp], aO[pp]);
                }
            }
        } else {
            const u64* XT = XB + (t & 1) * HSTRIDE;
            #pragma unroll
            for (int fo = 0; fo < 8; fo++) {
                const int f4 = fo * 4;
                u64 wv[4][4];
                {
                    ulonglong2 q;
                    q = *(const ulonglong2*)&WDX[xb0 + f4];     wv[0][0] = q.x; wv[0][1] = q.y;
                    q = *(const ulonglong2*)&WDX[xb0 + f4 + 2]; wv[0][2] = q.x; wv[0][3] = q.y;
                    q = *(const ulonglong2*)&WDX[xb1 + f4];     wv[1][0] = q.x; wv[1][1] = q.y;
                    q = *(const ulonglong2*)&WDX[xb1 + f4 + 2]; wv[1][2] = q.x; wv[1][3] = q.y;
                    q = *(const ulonglong2*)&WDX[xb2 + f4];     wv[2][0] = q.x; wv[2][1] = q.y;
                    q = *(const ulonglong2*)&WDX[xb2 + f4 + 2]; wv[2][2] = q.x; wv[2][3] = q.y;
                    q = *(const ulonglong2*)&WDX[xb3 + f4];     wv[3][0] = q.x; wv[3][1] = q.y;
                    q = *(const ulonglong2*)&WDX[xb3 + f4 + 2]; wv[3][2] = q.x; wv[3][3] = q.y;
                }
                u64 xv[4][4];
                #pragma unroll
                for (int fp = 0; fp < 4; fp++) {
                    ulonglong2 q0 = *(const ulonglong2*)&XT[(f4 + fp) * 34 + pg4];
                    ulonglong2 q1 = *(const ulonglong2*)&XT[(f4 + fp) * 34 + pg4 + 2];
                    xv[fp][0] = q0.x; xv[fp][1] = q0.y; xv[fp][2] = q1.x; xv[fp][3] = q1.y;
                }
                #pragma unroll
                for (int fp = 0; fp < 4; fp++) {
                    #pragma unroll
                    for (int pp = 0; pp < 4; pp++) {
                        aI[pp] = ffma2(wv[0][fp], xv[fp][pp], aI[pp]);
                        aF[pp] = ffma2(wv[1][fp], xv[fp][pp], aF[pp]);
                        aG[pp] = ffma2(wv[2][fp], xv[fp][pp], aG[pp]);
                        aO[pp] = ffma2(wv[3][fp], xv[fp][pp], aO[pp]);
                    }
                }
            }
        }

        // ---- activations: 8 peds, unit k ----
        float hvec[8];
        #pragma unroll
        for (int pp = 0; pp < 4; pp++) {
            {
                const int p = 2 * pp;
                float gi = lo2(aI[pp]) + bI, gf = lo2(aF[pp]) + bF;
                float gg = lo2(aG[pp]) + bG, go = lo2(aO[pp]) + bO;
                float cn = sigmf_(gf) * c[p] + sigmf_(gi) * tanhf_(gg);
                c[p] = cn;
                hvec[p] = sigmf_(go) * tanhf_(cn);
            }
            {
                const int p = 2 * pp + 1;
                float gi = hi2(aI[pp]) + bI, gf = hi2(aF[pp]) + bF;
                float gg = hi2(aG[pp]) + bG, go = hi2(aO[pp]) + bO;
                float cn = sigmf_(gf) * c[p] + sigmf_(gi) * tanhf_(gg);
                c[p] = cn;
                hvec[p] = sigmf_(go) * tanhf_(cn);
            }
        }

        // ---- stores: hsout (lane-contiguous, coalesced) ----
        const int pedbase = base + pg * 8;
        #pragma unroll
        for (int j = 0; j < 8; j++)
            hsout[((size_t)t * NTOT + pedbase + j) * 32 + k] = hvec[j];

        if (t < TT - 1) {
            // write next h tile
            u64* HN = HB + ((t + 1) & 1) * HSTRIDE + (size_t)k * 34 + pg4;
            #pragma unroll
            for (int jj = 0; jj < 4; jj++) HN[jj] = pk2(hvec[2*jj], hvec[2*jj+1]);

            if constexpr (D == 32) {
                // prefetch next step's x into the other buffer
                const float4* xp = reinterpret_cast<const float4*>(
                    xseq + ((size_t)(t + 1) * NTOT + base + xpp) * 32 + xpo);
                float4 A = xp[0], Bq = xp[1];
                float av[8] = {A.x, A.y, A.z, A.w, Bq.x, Bq.y, Bq.z, Bq.w};
                u32* XH = reinterpret_cast<u32*>(XB + ((t + 1) & 1) * HSTRIDE);
                #pragma unroll
                for (int e = 0; e < 8; e++)
                    XH[2 * ((xpo + e) * 34 + (xpp >> 1)) + (xpp & 1)] = __float_as_uint(av[e]);
            }
            __syncthreads();
        } else if (ENC) {
            #pragma unroll
            for (int j = 0; j < 8; j++) {
                float* ep = enc + (size_t)(pedbase + j) * 72;
                ep[32 + k] = hvec[j];
                ep[k] = traj_last[(size_t)(pedbase + j) * 32 + k];
            }
            if (k < 8) {
                const float z = znoise[(size_t)blockIdx.x * 8 + k];
                #pragma unroll
                for (int j = 0; j < 8; j++)
                    enc[(size_t)(pedbase + j) * 72 + 64 + k] = z;
            }
        }
    }
}

// ---------------------------------------------------------------------------
// GAT encoder: one block per (scene, t). 256 threads, 72.6 KB smem, 3 blk/SM.
// ---------------------------------------------------------------------------
#define GAT_SMEM_FLOATS 18160
#define GAT_SMEM_BYTES  (GAT_SMEM_FLOATS * 4)

__global__ void __launch_bounds__(256, 3) gat_kernel(
    const float* __restrict__ trajhs,   // [T, N, 32]
    const float* __restrict__ w0,       // [4,32,16]
    const float* __restrict__ asrc0, const float* __restrict__ adst0,  // [4,16]
    const float* __restrict__ bias0,    // [16]
    const float* __restrict__ w1,       // [1,64,32]
    const float* __restrict__ asrc1, const float* __restrict__ adst1,  // [32]
    const float* __restrict__ bias1,    // [32]
    float* __restrict__ gout)           // [T, N, 32]
{
    extern __shared__ __align__(16) float sm[];
    float* XN  = sm;           // 64 x 33           (dead after hp0)
    float* W0S = sm + 2112;    // 32 x 64           (dead after hp0)
    float* EM  = sm;           // 64 x 65           (overlays XN+W0S)
    float* HP0 = sm + 4160;    // 64 x 68
    float* S0  = sm + 8512;    // 4 x 64
    float* D0  = sm + 8768;    // 4 x 64
    float* X1  = sm + 9024;    // 64 x 68
    float* W1S = sm + 13376;   // 64 x 32
    float* HP1 = sm + 15424;   // 64 x 36
    float* S1  = sm + 17728;   // 64
    float* D1  = sm + 17792;   // 64
    float* ES  = sm + 17856;   // 64
    float* A0S = sm + 17920;   // 64
    float* A0D = sm + 17984;   // 64
    float* A1S = sm + 18048;   // 32
    float* A1D = sm + 18080;   // 32
    float* B0  = sm + 18112;   // 16
    float* B1  = sm + 18128;   // 32

    const int tid = threadIdx.x;
    const int b = blockIdx.x;
    const int s = b >> 3, t = b & 7;

    const float* src = trajhs + ((size_t)t * NTOT + s * 64) * 32;
    for (int i = tid; i < 2048; i += 256) XN[(i >> 5) * 33 + (i & 31)] = src[i];
    for (int i = tid; i < 2048; i += 256) {
        int f = i >> 6, cc = i & 63;
        W0S[i] = w0[((cc >> 4) << 9) + (f << 4) + (cc & 15)];
    }
    for (int i = tid; i < 2048; i += 256) W1S[i] = w1[i];
    if (tid < 64)       { A0S[tid] = asrc0[tid]; A0D[tid] = adst0[tid]; }
    else if (tid < 96)  { A1S[tid - 64] = asrc1[tid - 64]; A1D[tid - 64] = adst1[tid - 64]; }
    else if (tid < 112) { B0[tid - 96] = bias0[tid - 96]; }
    else if (tid < 144) { B1[tid - 112] = bias1[tid - 112]; }
    __syncthreads();

    // --- instance norm 0 ---
    {
        const int f = tid >> 3, g = tid & 7;
        float mval = 0.f;
        #pragma unroll
        for (int i = 0; i < 8; i++) mval += XN[(g + 8 * i) * 33 + f];
        mval += __shfl_xor_sync(0xFFFFFFFFu, mval, 1);
        mval += __shfl_xor_sync(0xFFFFFFFFu, mval, 2);
        mval += __shfl_xor_sync(0xFFFFFFFFu, mval, 4);
        const float m = mval * 0.015625f;
        float v = 0.f;
        #pragma unroll
        for (int i = 0; i < 8; i++) { float d = XN[(g + 8 * i) * 33 + f] - m; v = fmaf(d, d, v); }
        v += __shfl_xor_sync(0xFFFFFFFFu, v, 1);
        v += __shfl_xor_sync(0xFFFFFFFFu, v, 2);
        v += __shfl_xor_sync(0xFFFFFFFFu, v, 4);
        const float inv = rsqrtf(fmaf(v, 0.015625f, 1e-5f));
        #pragma unroll
        for (int i = 0; i < 8; i++) {
            const int idx = (g + 8 * i) * 33 + f;
            XN[idx] = (XN[idx] - m) * inv;
        }
    }
    __syncthreads();

    // --- hp0 = xn @ w0 ---
    {
        const int p  = tid >> 2;
        const int cb = (tid & 3) << 4;
        u64 acc[8] = {0, 0, 0, 0, 0, 0, 0, 0};
        #pragma unroll
        for (int f = 0; f < 32; f++) {
            float xv = XN[p * 33 + f];
            u64 xx = pk2(xv, xv);
            const ulonglong2* w = reinterpret_cast<const ulonglong2*>(W0S + f * 64 + cb);
            #pragma unroll
            for (int j = 0; j < 4; j++) {
                ulonglong2 ww = w[j];
                acc[2*j]   = ffma2(ww.x, xx, acc[2*j]);
                acc[2*j+1] = ffma2(ww.y, xx, acc[2*j+1]);
            }
        }
        u64* dst = reinterpret_cast<u64*>(HP0 + p * 68 + cb);
        #pragma unroll
        for (int j = 0; j < 8; j++) dst[j] = acc[j];
    }
    __syncthreads();

    // --- s0, d0 ---
    {
        const int h = tid >> 6, p = tid & 63;
        const float* hb = HP0 + p * 68 + h * 16;
        const float* as = A0S + h * 16;
        const float* ad = A0D + h * 16;
        float sv = 0.f, dv = 0.f;
        #pragma unroll
        for (int o = 0; o < 16; o++) {
            float hv = hb[o];
            sv = fmaf(hv, as[o], sv);
            dv = fmaf(hv, ad[o], dv);
        }
        S0[h * 64 + p] = sv;
        D0[h * 64 + p] = dv;
    }
    __syncthreads();

    // --- attention0 -> X1 ---
    {
        const int h = tid >> 6, p = tid & 63;
        const float sp = S0[h * 64 + p];
        const float* dd = D0 + h * 64;
        float mx = -3.4e38f;
        #pragma unroll 8
        for (int q = 0; q < 64; q++) {
            float e = sp + dd[q];
            e = e > 0.f ? e : 0.2f * e;
            mx = fmaxf(mx, e);
        }
        u64 acc[8] = {0, 0, 0, 0, 0, 0, 0, 0};
        float den = 0.f;
        #pragma unroll 2
        for (int q = 0; q < 64; q++) {
            float e = sp + dd[q];
            e = e > 0.f ? e : 0.2f * e;
            float w = __expf(e - mx);
            den += w;
            u64 ww = pk2(w, w);
            const ulonglong2* hq = reinterpret_cast<const ulonglong2*>(HP0 + q * 68 + h * 16);
            #pragma unroll
            for (int j = 0; j < 4; j++) {
                ulonglong2 hv = hq[j];
                acc[2*j]   = ffma2(hv.x, ww, acc[2*j]);
                acc[2*j+1] = ffma2(hv.y, ww, acc[2*j+1]);
            }
        }
        float inv = __fdividef(1.f, den);
        float* xo = X1 + p * 68 + h * 16;
        #pragma unroll
        for (int j = 0; j < 8; j++) {
            float v0 = fmaf(lo2(acc[j]), inv, B0[2 * j]);
            float v1 = fmaf(hi2(acc[j]), inv, B0[2 * j + 1]);
            v0 = v0 > 0.f ? v0 : expm1f(v0);
            v1 = v1 > 0.f ? v1 : expm1f(v1);
            xo[2 * j] = v0;
            xo[2 * j + 1] = v1;
        }
    }
    __syncthreads();

    // --- instance norm 1 ---
    {
        const int f = tid >> 2, g = tid & 3;
        float mval = 0.f;
        #pragma unroll
        for (int i = 0; i < 16; i++) mval += X1[(g + 4 * i) * 68 + f];
        mval += __shfl_xor_sync(0xFFFFFFFFu, mval, 1);
        mval += __shfl_xor_sync(0xFFFFFFFFu, mval, 2);
        const float m = mval * 0.015625f;
        float v = 0.f;
        #pragma unroll
        for (int i = 0; i < 16; i++) { float d = X1[(g + 4 * i) * 68 + f] - m; v = fmaf(d, d, v); }
        v += __shfl_xor_sync(0xFFFFFFFFu, v, 1);
        v += __shfl_xor_sync(0xFFFFFFFFu, v, 2);
        const float inv = rsqrtf(fmaf(v, 0.015625f, 1e-5f));
        #pragma unroll
        for (int i = 0; i < 16; i++) {
            const int idx = (g + 4 * i) * 68 + f;
            X1[idx] = (X1[idx] - m) * inv;
        }
    }
    __syncthreads();

    // --- hp1 = x1 @ w1 ---
    {
        const int p  = tid >> 2;
        const int ob = (tid & 3) << 3;
        u64 acc[4] = {0, 0, 0, 0};
        #pragma unroll
        for (int f = 0; f < 64; f++) {
            float xv = X1[p * 68 + f];
            u64 xx = pk2(xv, xv);
            const ulonglong2* w = reinterpret_cast<const ulonglong2*>(W1S + f * 32 + ob);
            #pragma unroll
            for (int j = 0; j < 2; j++) {
                ulonglong2 ww = w[j];
                acc[2*j]   = ffma2(ww.x, xx, acc[2*j]);
                acc[2*j+1] = ffma2(ww.y, xx, acc[2*j+1]);
            }
        }
        u64* dst = reinterpret_cast<u64*>(HP1 + p * 36 + ob);
        #pragma unroll
        for (int j = 0; j < 4; j++) dst[j] = acc[j];
    }
    __syncthreads();

    // --- s1, d1 ---
    if (tid < 128) {
        const int p = tid & 63;
        const bool ds = tid >= 64;
        const float* a = ds ? A1D : A1S;
        const float* hb = HP1 + p * 36;
        float sv = 0.f;
        #pragma unroll
        for (int o = 0; o < 32; o++) sv = fmaf(hb[o], a[o], sv);
        (ds ? D1 : S1)[p] = sv;
    }
    __syncthreads();

    // --- softmax weights layer 1 ---
    {
        const int p = tid >> 2, qh = tid & 3;
        const float sp = S1[p];
        float mx = -3.4e38f;
        #pragma unroll
        for (int qi = 0; qi < 16; qi++) {
            float e = sp + D1[qh * 16 + qi];
            e = e > 0.f ? e : 0.2f * e;
            mx = fmaxf(mx, e);
        }
        mx = fmaxf(mx, __shfl_xor_sync(0xFFFFFFFFu, mx, 1));
        mx = fmaxf(mx, __shfl_xor_sync(0xFFFFFFFFu, mx, 2));
        float den = 0.f;
        #pragma unroll
        for (int qi = 0; qi < 16; qi++) {
            const int q = qh * 16 + qi;
            float e = sp + D1[q];
            e = e > 0.f ? e : 0.2f * e;
            float w = __expf(e - mx);
            EM[p * 65 + q] = w;
            den += w;
        }
        den += __shfl_xor_sync(0xFFFFFFFFu, den, 1);
        den += __shfl_xor_sync(0xFFFFFFFFu, den, 2);
        if (qh == 0) ES[p] = __fdividef(1.f, den);
    }
    __syncthreads();

    // --- apply attn1, write graph_in ---
    {
        const int p  = tid >> 2;
        const int ob = (tid & 3) << 3;
        u64 acc[4] = {0, 0, 0, 0};
        const float* ew = EM + p * 65;
        #pragma unroll 2
        for (int q = 0; q < 64; q++) {
            float w = ew[q];
            u64 ww = pk2(w, w);
            const ulonglong2* hq = reinterpret_cast<const ulonglong2*>(HP1 + q * 36 + ob);
            #pragma unroll
            for (int j = 0; j < 2; j++) {
                ulonglong2 hv = hq[j];
                acc[2*j]   = ffma2(hv.x, ww, acc[2*j]);
                acc[2*j+1] = ffma2(hv.y, ww, acc[2*j+1]);
            }
        }
        float inv = ES[p];
        float2* gp = reinterpret_cast<float2*>(
            gout + ((size_t)t * NTOT + s * 64 + p) * 32 + ob);
        #pragma unroll
        for (int j = 0; j < 4; j++) {
            float v0 = fmaf(lo2(acc[j]), inv, B1[ob + 2 * j]);
            float v1 = fmaf(hi2(acc[j]), inv, B1[ob + 2 * j + 1]);
            gp[j] = make_float2(v0, v1);
        }
    }
}

// ---------------------------------------------------------------------------
#define LSTM3_SMEM_BYTES  ((128*34 + 128*5  + 2*32*34 + 8*3*34) * 8)
#define LSTM32_SMEM_BYTES ((128*34 + 128*34 + 2*32*34 + 2*32*34) * 8)

extern "C" void kernel_launch(void* const* d_in, const int* in_sizes, int n_in,
                              void* d_out, int out_size)
{
    (void)in_sizes; (void)n_in; (void)out_size;
    const float* obs  = (const float*)d_in[0];
    const float* h0t  = (const float*)d_in[1];
    const float* c0t  = (const float*)d_in[2];
    const float* h0g  = (const float*)d_in[3];
    const float* c0g  = (const float*)d_in[4];
    const float* zn   = (const float*)d_in[5];
    const float* WihT = (const float*)d_in[6];
    const float* WhhT = (const float*)d_in[7];
    const float* bihT = (const float*)d_in[8];
    const float* bhhT = (const float*)d_in[9];
    const float* WihG = (const float*)d_in[10];
    const float* WhhG = (const float*)d_in[11];
    const float* bihG = (const float*)d_in[12];
    const float* bhhG = (const float*)d_in[13];
    const float* w0   = (const float*)d_in[14];
    const float* as0  = (const float*)d_in[15];
    const float* ad0  = (const float*)d_in[16];
    const float* b0   = (const float*)d_in[17];
    const float* w1   = (const float*)d_in[18];
    const float* as1  = (const float*)d_in[19];
    const float* ad1  = (const float*)d_in[20];
    const float* b1   = (const float*)d_in[21];

    float* out = (float*)d_out;
    float* enc = out;                                  // [N,72]
    float* ghs = out + (size_t)NTOT * 72;              // [T,N,32]
    float* ths = ghs + (size_t)TT * NTOT * 32;         // [T,N,32]

    float* gin = nullptr;
    cudaGetSymbolAddress((void**)&gin, g_graph_in);

    cudaFuncSetAttribute(lstm_kernel<3, false>,
                         cudaFuncAttributeMaxDynamicSharedMemorySize, LSTM3_SMEM_BYTES);
    cudaFuncSetAttribute(lstm_kernel<32, true>,
                         cudaFuncAttributeMaxDynamicSharedMemorySize, LSTM32_SMEM_BYTES);
    cudaFuncSetAttribute(gat_kernel,
                         cudaFuncAttributeMaxDynamicSharedMemorySize, GAT_SMEM_BYTES);

    // 1) traj LSTM -> traj_hs (directly into output region)
    lstm_kernel<3, false><<<NTOT / 64, 256, LSTM3_SMEM_BYTES>>>(
        obs, h0t, c0t, WihT, WhhT, bihT, bhhT, ths, nullptr, nullptr, nullptr);

    // 2) GAT encoder -> graph_in scratch
    gat_kernel<<<NS * TT, 256, GAT_SMEM_BYTES>>>(
        ths, w0, as0, ad0, b0, w1, as1, ad1, b1, gin);

    // 3) graph LSTM -> graph_hs + encoded (traj_hs[-1] | graph_hs[-1] | noise)
    lstm_kernel<32, true><<<NTOT / 64, 256, LSTM32_SMEM_BYTES>>>(
        gin, h0g, c0g, WihG, WhhG, bihG, bhhG, ghs,
        ths + (size_t)(TT - 1) * NTOT * 32, zn, enc);
}

// round 13
// speedup vs baseline: 1.8818x; 1.0052x over previous
#include <cuda_runtime.h>

#define TT   8
#define NS   512
#define NTOT 32768   // NS*NP

// Scratch for GAT output -> graph LSTM input ([T, N, 32])
__device__ float g_graph_in[(size_t)TT * NTOT * 32];

typedef unsigned long long u64;
typedef unsigned int u32;

__device__ __forceinline__ u64 ffma2(u64 a, u64 b, u64 c) {
    u64 d;
    asm("fma.rn.f32x2 %0, %1, %2, %3;" : "=l"(d) : "l"(a), "l"(b), "l"(c));
    return d;
}
__device__ __forceinline__ u64 pk2(float lo, float hi) {
    u64 r;
    asm("mov.b64 %0, {%1, %2};" : "=l"(r) : "f"(lo), "f"(hi));
    return r;
}
__device__ __forceinline__ float lo2(u64 v) { return __uint_as_float((unsigned)v); }
__device__ __forceinline__ float hi2(u64 v) { return __uint_as_float((unsigned)(v >> 32)); }

__device__ __forceinline__ float sigmf_(float x) {
    return __fdividef(1.f, 1.f + __expf(-x));
}
__device__ __forceinline__ float tanhf_(float x) {
    float e = __expf(-2.f * fabsf(x));
    float r = __fdividef(1.f - e, 1.f + e);
    return copysignf(r, x);
}

// ---------------------------------------------------------------------------
// LSTM as per-step tiled GEMM (unchanged from R12).
// ---------------------------------------------------------------------------
template<int D, bool ENC>
__global__ void __launch_bounds__(256, 2) lstm_kernel(
    const float* __restrict__ xseq,    // [T, N, D]
    const float* __restrict__ h0, const float* __restrict__ c0,   // [N,32]
    const float* __restrict__ Wih,     // [128, D]
    const float* __restrict__ Whh,     // [128, 32]
    const float* __restrict__ bih, const float* __restrict__ bhh, // [128]
    float* __restrict__ hsout,         // [T, N, 32]
    const float* __restrict__ traj_last, // [N,32] (ENC only)
    const float* __restrict__ znoise,    // [S,8]  (ENC only)
    float* __restrict__ enc)             // [N,72] (ENC only)
{
    constexpr int SWH   = 34;
    constexpr int SWX   = (D == 3) ? 5 : 34;
    constexpr int WDH_SZ = 128 * SWH;
    constexpr int WDX_SZ = 128 * SWX;
    constexpr int HB_SZ  = 2 * 32 * 34;
    constexpr int HSTRIDE = 32 * 34;

    extern __shared__ __align__(16) u64 smU[];
    u64* WDH = smU;
    u64* WDX = WDH + WDH_SZ;
    u64* HB  = WDX + WDX_SZ;
    u64* XB  = HB + HB_SZ;

    const int tid  = threadIdx.x;
    const int k    = tid & 31;
    const int pg   = tid >> 5;
    const int pg4  = pg * 4;
    const int base = blockIdx.x * 64;

    for (int i = tid; i < 128 * 32; i += 256) {
        int r = i >> 5, f = i & 31;
        float w = Whh[r * 32 + f];
        WDH[r * SWH + f] = pk2(w, w);
    }
    if constexpr (D == 3) {
        for (int i = tid; i < 128 * 3; i += 256) {
            int r = i / 3, f = i - r * 3;
            float w = Wih[r * 3 + f];
            WDX[r * SWX + f] = pk2(w, w);
        }
    } else {
        for (int i = tid; i < 128 * 32; i += 256) {
            int r = i >> 5, f = i & 31;
            float w = Wih[r * 32 + f];
            WDX[r * SWX + f] = pk2(w, w);
        }
    }

    const float bI = bih[k]      + bhh[k];
    const float bF = bih[32 + k] + bhh[32 + k];
    const float bG = bih[64 + k] + bhh[64 + k];
    const float bO = bih[96 + k] + bhh[96 + k];

    float c[8];
    {
        float hv0[8];
        #pragma unroll
        for (int j = 0; j < 8; j++) {
            c[j]   = c0[(size_t)(base + pg * 8 + j) * 32 + k];
            hv0[j] = h0[(size_t)(base + pg * 8 + j) * 32 + k];
        }
        u64* HN = HB + (size_t)k * 34 + pg4;
        #pragma unroll
        for (int jj = 0; jj < 4; jj++) HN[jj] = pk2(hv0[2*jj], hv0[2*jj+1]);
    }

    const int xpp = tid >> 2;
    const int xpo = (tid & 3) << 3;
    if constexpr (D == 3) {
        u32* XH = reinterpret_cast<u32*>(XB);
        for (int i = tid; i < 8 * 64 * 3; i += 256) {
            int tt  = i / 192;
            int rem = i - tt * 192;
            int p   = rem / 3;
            int xf  = rem - p * 3;
            float xv = xseq[((size_t)tt * NTOT + base + p) * 3 + xf];
            XH[2 * ((tt * 3 + xf) * 34 + (p >> 1)) + (p & 1)] = __float_as_uint(xv);
        }
    } else {
        const float4* xp = reinterpret_cast<const float4*>(
            xseq + ((size_t)base + xpp) * 32 + xpo);
        float4 A = xp[0], Bq = xp[1];
        float av[8] = {A.x, A.y, A.z, A.w, Bq.x, Bq.y, Bq.z, Bq.w};
        u32* XH = reinterpret_cast<u32*>(XB);
        #pragma unroll
        for (int e = 0; e < 8; e++)
            XH[2 * ((xpo + e) * 34 + (xpp >> 1)) + (xpp & 1)] = __float_as_uint(av[e]);
    }
    __syncthreads();

    const int kb0 = (0 * 32 + k) * SWH;
    const int kb1 = (1 * 32 + k) * SWH;
    const int kb2 = (2 * 32 + k) * SWH;
    const int kb3 = (3 * 32 + k) * SWH;
    const int xb0 = (0 * 32 + k) * SWX;
    const int xb1 = (1 * 32 + k) * SWX;
    const int xb2 = (2 * 32 + k) * SWX;
    const int xb3 = (3 * 32 + k) * SWX;

    #pragma unroll 1
    for (int t = 0; t < TT; t++) {
        u64 aI[4] = {0,0,0,0}, aF[4] = {0,0,0,0}, aG[4] = {0,0,0,0}, aO[4] = {0,0,0,0};

        const u64* HT = HB + (t & 1) * HSTRIDE;
        #pragma unroll
        for (int fo = 0; fo < 8; fo++) {
            const int f4 = fo * 4;
            u64 wv[4][4];
            {
                ulonglong2 q;
                q = *(const ulonglong2*)&WDH[kb0 + f4];     wv[0][0] = q.x; wv[0][1] = q.y;
                q = *(const ulonglong2*)&WDH[kb0 + f4 + 2]; wv[0][2] = q.x; wv[0][3] = q.y;
                q = *(const ulonglong2*)&WDH[kb1 + f4];     wv[1][0] = q.x; wv[1][1] = q.y;
                q = *(const ulonglong2*)&WDH[kb1 + f4 + 2]; wv[1][2] = q.x; wv[1][3] = q.y;
                q = *(const ulonglong2*)&WDH[kb2 + f4];     wv[2][0] = q.x; wv[2][1] = q.y;
                q = *(const ulonglong2*)&WDH[kb2 + f4 + 2]; wv[2][2] = q.x; wv[2][3] = q.y;
                q = *(const ulonglong2*)&WDH[kb3 + f4];     wv[3][0] = q.x; wv[3][1] = q.y;
                q = *(const ulonglong2*)&WDH[kb3 + f4 + 2]; wv[3][2] = q.x; wv[3][3] = q.y;
            }
            u64 hv[4][4];
            #pragma unroll
            for (int fp = 0; fp < 4; fp++) {
                ulonglong2 q0 = *(const ulonglong2*)&HT[(f4 + fp) * 34 + pg4];
                ulonglong2 q1 = *(const ulonglong2*)&HT[(f4 + fp) * 34 + pg4 + 2];
                hv[fp][0] = q0.x; hv[fp][1] = q0.y; hv[fp][2] = q1.x; hv[fp][3] = q1.y;
            }
            #pragma unroll
            for (int fp = 0; fp < 4; fp++) {
                #pragma unroll
                for (int pp = 0; pp < 4; pp++) {
                    aI[pp] = ffma2(wv[0][fp], hv[fp][pp], aI[pp]);
                    aF[pp] = ffma2(wv[1][fp], hv[fp][pp], aF[pp]);
                    aG[pp] = ffma2(wv[2][fp], hv[fp][pp], aG[pp]);
                    aO[pp] = ffma2(wv[3][fp], hv[fp][pp], aO[pp]);
                }
            }
        }

        if constexpr (D == 3) {
            const u64* XT = XB + (size_t)t * (3 * 34);
            #pragma unroll
            for (int xf = 0; xf < 3; xf++) {
                u64 wI = WDX[xb0 + xf], wF = WDX[xb1 + xf];
                u64 wG = WDX[xb2 + xf], wO = WDX[xb3 + xf];
                ulonglong2 q0 = *(const ulonglong2*)&XT[xf * 34 + pg4];
                ulonglong2 q1 = *(const ulonglong2*)&XT[xf * 34 + pg4 + 2];
                u64 xv[4] = {q0.x, q0.y, q1.x, q1.y};
                #pragma unroll
                for (int pp = 0; pp < 4; pp++) {
                    aI[pp] = ffma2(wI, xv[pp], aI[pp]);
                    aF[pp] = ffma2(wF, xv[pp], aF[pp]);
                    aG[pp] = ffma2(wG, xv[pp], aG[pp]);
                    aO[pp] = ffma2(wO, xv[pp], aO[pp]);
                }
            }
        } else {
            const u64* XT = XB + (t & 1) * HSTRIDE;
            #pragma unroll
            for (int fo = 0; fo < 8; fo++) {
                const int f4 = fo * 4;
                u64 wv[4][4];
                {
                    ulonglong2 q;
                    q = *(const ulonglong2*)&WDX[xb0 + f4];     wv[0][0] = q.x; wv[0][1] = q.y;
                    q = *(const ulonglong2*)&WDX[xb0 + f4 + 2]; wv[0][2] = q.x; wv[0][3] = q.y;
                    q = *(const ulonglong2*)&WDX[xb1 + f4];     wv[1][0] = q.x; wv[1][1] = q.y;
                    q = *(const ulonglong2*)&WDX[xb1 + f4 + 2]; wv[1][2] = q.x; wv[1][3] = q.y;
                    q = *(const ulonglong2*)&WDX[xb2 + f4];     wv[2][0] = q.x; wv[2][1] = q.y;
                    q = *(const ulonglong2*)&WDX[xb2 + f4 + 2]; wv[2][2] = q.x; wv[2][3] = q.y;
                    q = *(const ulonglong2*)&WDX[xb3 + f4];     wv[3][0] = q.x; wv[3][1] = q.y;
                    q = *(const ulonglong2*)&WDX[xb3 + f4 + 2]; wv[3][2] = q.x; wv[3][3] = q.y;
                }
                u64 xv[4][4];
                #pragma unroll
                for (int fp = 0; fp < 4; fp++) {
                    ulonglong2 q0 = *(const ulonglong2*)&XT[(f4 + fp) * 34 + pg4];
                    ulonglong2 q1 = *(const ulonglong2*)&XT[(f4 + fp) * 34 + pg4 + 2];
                    xv[fp][0] = q0.x; xv[fp][1] = q0.y; xv[fp][2] = q1.x; xv[fp][3] = q1.y;
                }
                #pragma unroll
                for (int fp = 0; fp < 4; fp++) {
                    #pragma unroll
                    for (int pp = 0; pp < 4; pp++) {
                        aI[pp] = ffma2(wv[0][fp], xv[fp][pp], aI[pp]);
                        aF[pp] = ffma2(wv[1][fp], xv[fp][pp], aF[pp]);
                        aG[pp] = ffma2(wv[2][fp], xv[fp][pp], aG[pp]);
                        aO[pp] = ffma2(wv[3][fp], xv[fp][pp], aO[pp]);
                    }
                }
            }
        }

        float hvec[8];
        #pragma unroll
        for (int pp = 0; pp < 4; pp++) {
            {
                const int p = 2 * pp;
                float gi = lo2(aI[pp]) + bI, gf = lo2(aF[pp]) + bF;
                float gg = lo2(aG[pp]) + bG, go = lo2(aO[pp]) + bO;
                float cn = sigmf_(gf) * c[p] + sigmf_(gi) * tanhf_(gg);
                c[p] = cn;
                hvec[p] = sigmf_(go) * tanhf_(cn);
            }
            {
                const int p = 2 * pp + 1;
                float gi = hi2(aI[pp]) + bI, gf = hi2(aF[pp]) + bF;
                float gg = hi2(aG[pp]) + bG, go = hi2(aO[pp]) + bO;
                float cn = sigmf_(gf) * c[p] + sigmf_(gi) * tanhf_(gg);
                c[p] = cn;
                hvec[p] = sigmf_(go) * tanhf_(cn);
            }
        }

        const int pedbase = base + pg * 8;
        #pragma unroll
        for (int j = 0; j < 8; j++)
            hsout[((size_t)t * NTOT + pedbase + j) * 32 + k] = hvec[j];

        if (t < TT - 1) {
            u64* HN = HB + ((t + 1) & 1) * HSTRIDE + (size_t)k * 34 + pg4;
            #pragma unroll
            for (int jj = 0; jj < 4; jj++) HN[jj] = pk2(hvec[2*jj], hvec[2*jj+1]);

            if constexpr (D == 32) {
                const float4* xp = reinterpret_cast<const float4*>(
                    xseq + ((size_t)(t + 1) * NTOT + base + xpp) * 32 + xpo);
                float4 A = xp[0], Bq = xp[1];
                float av[8] = {A.x, A.y, A.z, A.w, Bq.x, Bq.y, Bq.z, Bq.w};
                u32* XH = reinterpret_cast<u32*>(XB + ((t + 1) & 1) * HSTRIDE);
                #pragma unroll
                for (int e = 0; e < 8; e++)
                    XH[2 * ((xpo + e) * 34 + (xpp >> 1)) + (xpp & 1)] = __float_as_uint(av[e]);
            }
            __syncthreads();
        } else if (ENC) {
            #pragma unroll
            for (int j = 0; j < 8; j++) {
                float* ep = enc + (size_t)(pedbase + j) * 72;
                ep[32 + k] = hvec[j];
                ep[k] = traj_last[(size_t)(pedbase + j) * 32 + k];
            }
            if (k < 8) {
                const float z = znoise[(size_t)blockIdx.x * 8 + k];
                #pragma unroll
                for (int j = 0; j < 8; j++)
                    enc[(size_t)(pedbase + j) * 72 + 64 + k] = z;
            }
        }
    }
}

// ---------------------------------------------------------------------------
// GAT encoder v2: fused s/d epilogues, no softmax max-pass, batched exp,
// EM overlays dead HP0 (stride 68, float4-aligned). 8 barriers total.
// ---------------------------------------------------------------------------
#define GAT_SMEM_FLOATS 18160
#define GAT_SMEM_BYTES  (GAT_SMEM_FLOATS * 4)

__global__ void __launch_bounds__(256, 3) gat_kernel(
    const float* __restrict__ trajhs,   // [T, N, 32]
    const float* __restrict__ w0,       // [4,32,16]
    const float* __restrict__ asrc0, const float* __restrict__ adst0,  // [4,16]
    const float* __restrict__ bias0,    // [16]
    const float* __restrict__ w1,       // [1,64,32]
    const float* __restrict__ asrc1, const float* __restrict__ adst1,  // [32]
    const float* __restrict__ bias1,    // [32]
    float* __restrict__ gout)           // [T, N, 32]
{
    extern __shared__ __align__(16) float sm[];
    float* XN  = sm;           // 64 x 33   (dead after hp0)
    float* W0S = sm + 2112;    // 32 x 64   (dead after hp0)
    float* HP0 = sm + 4160;    // 64 x 68   (dead after attn0)
    float* EM  = sm + 4160;    // 64 x 68   overlays HP0
    float* S0  = sm + 8512;    // 4 x 64
    float* D0  = sm + 8768;    // 4 x 64
    float* X1  = sm + 9024;    // 64 x 68
    float* W1S = sm + 13376;   // 64 x 32
    float* HP1 = sm + 15424;   // 64 x 36
    float* S1  = sm + 17728;   // 64
    float* D1  = sm + 17792;   // 64
    float* ES  = sm + 17856;   // 64
    float* A0S = sm + 17920;   // 64
    float* A0D = sm + 17984;   // 64
    float* A1S = sm + 18048;   // 32
    float* A1D = sm + 18080;   // 32
    float* B0  = sm + 18112;   // 16
    float* B1  = sm + 18128;   // 32

    const int tid = threadIdx.x;
    const int b = blockIdx.x;
    const int s = b >> 3, t = b & 7;

    const float* src = trajhs + ((size_t)t * NTOT + s * 64) * 32;
    for (int i = tid; i < 2048; i += 256) XN[(i >> 5) * 33 + (i & 31)] = src[i];
    for (int i = tid; i < 2048; i += 256) {
        int f = i >> 6, cc = i & 63;
        W0S[i] = w0[((cc >> 4) << 9) + (f << 4) + (cc & 15)];
    }
    for (int i = tid; i < 2048; i += 256) W1S[i] = w1[i];
    if (tid < 64)       { A0S[tid] = asrc0[tid]; A0D[tid] = adst0[tid]; }
    else if (tid < 96)  { A1S[tid - 64] = asrc1[tid - 64]; A1D[tid - 64] = adst1[tid - 64]; }
    else if (tid < 112) { B0[tid - 96] = bias0[tid - 96]; }
    else if (tid < 144) { B1[tid - 112] = bias1[tid - 112]; }
    __syncthreads();

    // --- instance norm 0 ---
    {
        const int f = tid >> 3, g = tid & 7;
        float mval = 0.f;
        #pragma unroll
        for (int i = 0; i < 8; i++) mval += XN[(g + 8 * i) * 33 + f];
        mval += __shfl_xor_sync(0xFFFFFFFFu, mval, 1);
        mval += __shfl_xor_sync(0xFFFFFFFFu, mval, 2);
        mval += __shfl_xor_sync(0xFFFFFFFFu, mval, 4);
        const float m = mval * 0.015625f;
        float v = 0.f;
        #pragma unroll
        for (int i = 0; i < 8; i++) { float d = XN[(g + 8 * i) * 33 + f] - m; v = fmaf(d, d, v); }
        v += __shfl_xor_sync(0xFFFFFFFFu, v, 1);
        v += __shfl_xor_sync(0xFFFFFFFFu, v, 2);
        v += __shfl_xor_sync(0xFFFFFFFFu, v, 4);
        const float inv = rsqrtf(fmaf(v, 0.015625f, 1e-5f));
        #pragma unroll
        for (int i = 0; i < 8; i++) {
            const int idx = (g + 8 * i) * 33 + f;
            XN[idx] = (XN[idx] - m) * inv;
        }
    }
    __syncthreads();

    // --- hp0 = xn @ w0, FUSED s0/d0 from registers ---
    {
        const int p  = tid >> 2;
        const int h  = tid & 3;
        const int cb = h << 4;
        u64 acc[8] = {0, 0, 0, 0, 0, 0, 0, 0};
        #pragma unroll
        for (int f = 0; f < 32; f++) {
            float xv = XN[p * 33 + f];
            u64 xx = pk2(xv, xv);
            const ulonglong2* w = reinterpret_cast<const ulonglong2*>(W0S + f * 64 + cb);
            #pragma unroll
            for (int j = 0; j < 4; j++) {
                ulonglong2 ww = w[j];
                acc[2*j]   = ffma2(ww.x, xx, acc[2*j]);
                acc[2*j+1] = ffma2(ww.y, xx, acc[2*j+1]);
            }
        }
        float sv = 0.f, dv = 0.f;
        #pragma unroll
        for (int j = 0; j < 8; j++) {
            float v0 = lo2(acc[j]), v1 = hi2(acc[j]);
            sv = fmaf(v0, A0S[cb + 2*j], sv); sv = fmaf(v1, A0S[cb + 2*j + 1], sv);
            dv = fmaf(v0, A0D[cb + 2*j], dv); dv = fmaf(v1, A0D[cb + 2*j + 1], dv);
        }
        S0[h * 64 + p] = sv;
        D0[h * 64 + p] = dv;
        u64* dst = reinterpret_cast<u64*>(HP0 + p * 68 + cb);
        #pragma unroll
        for (int j = 0; j < 8; j++) dst[j] = acc[j];
    }
    __syncthreads();

    // --- attention0 (no max-pass, batched exp) -> X1 ---
    {
        const int h = tid >> 6, p = tid & 63;
        const float sp = S0[h * 64 + p];
        const float* dd = D0 + h * 64;
        u64 acc[8] = {0, 0, 0, 0, 0, 0, 0, 0};
        float den = 0.f;
        #pragma unroll 1
        for (int qb = 0; qb < 8; qb++) {
            float4 da = *(const float4*)(dd + qb * 8);
            float4 db = *(const float4*)(dd + qb * 8 + 4);
            float e[8] = {da.x, da.y, da.z, da.w, db.x, db.y, db.z, db.w};
            float w[8];
            #pragma unroll
            for (int i = 0; i < 8; i++) {
                float ev = sp + e[i];
                ev = ev > 0.f ? ev : 0.2f * ev;
                w[i] = __expf(ev);
            }
            #pragma unroll
            for (int i = 0; i < 8; i++) den += w[i];
            #pragma unroll
            for (int i = 0; i < 8; i++) {
                u64 ww = pk2(w[i], w[i]);
                const ulonglong2* hq = reinterpret_cast<const ulonglong2*>(
                    HP0 + (qb * 8 + i) * 68 + h * 16);
                ulonglong2 h0q = hq[0], h1q = hq[1], h2q = hq[2], h3q = hq[3];
                acc[0] = ffma2(h0q.x, ww, acc[0]); acc[1] = ffma2(h0q.y, ww, acc[1]);
                acc[2] = ffma2(h1q.x, ww, acc[2]); acc[3] = ffma2(h1q.y, ww, acc[3]);
                acc[4] = ffma2(h2q.x, ww, acc[4]); acc[5] = ffma2(h2q.y, ww, acc[5]);
                acc[6] = ffma2(h3q.x, ww, acc[6]); acc[7] = ffma2(h3q.y, ww, acc[7]);
            }
        }
        float inv = __fdividef(1.f, den);
        float* xo = X1 + p * 68 + h * 16;
        #pragma unroll
        for (int j = 0; j < 8; j++) {
            float v0 = fmaf(lo2(acc[j]), inv, B0[2 * j]);
            float v1 = fmaf(hi2(acc[j]), inv, B0[2 * j + 1]);
            v0 = v0 > 0.f ? v0 : expm1f(v0);
            v1 = v1 > 0.f ? v1 : expm1f(v1);
            xo[2 * j] = v0;
            xo[2 * j + 1] = v1;
        }
    }
    __syncthreads();

    // --- instance norm 1 ---
    {
        const int f = tid >> 2, g = tid & 3;
        float mval = 0.f;
        #pragma unroll
        for (int i = 0; i < 16; i++) mval += X1[(g + 4 * i) * 68 + f];
        mval += __shfl_xor_sync(0xFFFFFFFFu, mval, 1);
        mval += __shfl_xor_sync(0xFFFFFFFFu, mval, 2);
        const float m = mval * 0.015625f;
        float v = 0.f;
        #pragma unroll
        for (int i = 0; i < 16; i++) { float d = X1[(g + 4 * i) * 68 + f] - m; v = fmaf(d, d, v); }
        v += __shfl_xor_sync(0xFFFFFFFFu, v, 1);
        v += __shfl_xor_sync(0xFFFFFFFFu, v, 2);
        const float inv = rsqrtf(fmaf(v, 0.015625f, 1e-5f));
        #pragma unroll
        for (int i = 0; i < 16; i++) {
            const int idx = (g + 4 * i) * 68 + f;
            X1[idx] = (X1[idx] - m) * inv;
        }
    }
    __syncthreads();

    // --- hp1 = x1 @ w1, FUSED s1/d1 via shfl partial reduction ---
    {
        const int p  = tid >> 2;
        const int j4 = tid & 3;
        const int ob = j4 << 3;
        u64 acc[4] = {0, 0, 0, 0};
        #pragma unroll
        for (int f = 0; f < 64; f++) {
            float xv = X1[p * 68 + f];
            u64 xx = pk2(xv, xv);
            const ulonglong2* w = reinterpret_cast<const ulonglong2*>(W1S + f * 32 + ob);
            #pragma unroll
            for (int j = 0; j < 2; j++) {
                ulonglong2 ww = w[j];
                acc[2*j]   = ffma2(ww.x, xx, acc[2*j]);
                acc[2*j+1] = ffma2(ww.y, xx, acc[2*j+1]);
            }
        }
        float sv = 0.f, dv = 0.f;
        #pragma unroll
        for (int j = 0; j < 4; j++) {
            float v0 = lo2(acc[j]), v1 = hi2(acc[j]);
            sv = fmaf(v0, A1S[ob + 2*j], sv); sv = fmaf(v1, A1S[ob + 2*j + 1], sv);
            dv = fmaf(v0, A1D[ob + 2*j], dv); dv = fmaf(v1, A1D[ob + 2*j + 1], dv);
        }
        sv += __shfl_xor_sync(0xFFFFFFFFu, sv, 1);
        sv += __shfl_xor_sync(0xFFFFFFFFu, sv, 2);
        dv += __shfl_xor_sync(0xFFFFFFFFu, dv, 1);
        dv += __shfl_xor_sync(0xFFFFFFFFu, dv, 2);
        if (j4 == 0) { S1[p] = sv; D1[p] = dv; }
        u64* dst = reinterpret_cast<u64*>(HP1 + p * 36 + ob);
        #pragma unroll
        for (int j = 0; j < 4; j++) dst[j] = acc[j];
    }
    __syncthreads();

    // --- softmax1 weights (no max-pass; EM overlays dead HP0, stride 68) ---
    {
        const int p = tid >> 2, qh = tid & 3;
        const float sp = S1[p];
        const float* dq = D1 + qh * 16;
        float den = 0.f;
        #pragma unroll
        for (int v4 = 0; v4 < 4; v4++) {
            float4 dv4 = *(const float4*)(dq + v4 * 4);
            float e[4] = {dv4.x, dv4.y, dv4.z, dv4.w};
            float w[4];
            #pragma unroll
            for (int i = 0; i < 4; i++) {
                float ev = sp + e[i];
                ev = ev > 0.f ? ev : 0.2f * ev;
                w[i] = __expf(ev);
                den += w[i];
            }
            *(float4*)(EM + p * 68 + qh * 16 + v4 * 4) = make_float4(w[0], w[1], w[2], w[3]);
        }
        den += __shfl_xor_sync(0xFFFFFFFFu, den, 1);
        den += __shfl_xor_sync(0xFFFFFFFFu, den, 2);
        if (qh == 0) ES[p] = __fdividef(1.f, den);
    }
    __syncthreads();

    // --- apply attn1, write graph_in ---
    {
        const int p  = tid >> 2;
        const int ob = (tid & 3) << 3;
        u64 acc[4] = {0, 0, 0, 0};
        const float* ew = EM + p * 68;
        #pragma unroll 2
        for (int qb = 0; qb < 16; qb++) {
            float4 w4 = *(const float4*)(ew + qb * 4);
            float wv[4] = {w4.x, w4.y, w4.z, w4.w};
            #pragma unroll
            for (int i = 0; i < 4; i++) {
                u64 ww = pk2(wv[i], wv[i]);
                const ulonglong2* hq = reinterpret_cast<const ulonglong2*>(
                    HP1 + (qb * 4 + i) * 36 + ob);
                ulonglong2 h0q = hq[0], h1q = hq[1];
                acc[0] = ffma2(h0q.x, ww, acc[0]); acc[1] = ffma2(h0q.y, ww, acc[1]);
                acc[2] = ffma2(h1q.x, ww, acc[2]); acc[3] = ffma2(h1q.y, ww, acc[3]);
            }
        }
        float inv = ES[p];
        float2* gp = reinterpret_cast<float2*>(
            gout + ((size_t)t * NTOT + s * 64 + p) * 32 + ob);
        #pragma unroll
        for (int j = 0; j < 4; j++) {
            float v0 = fmaf(lo2(acc[j]), inv, B1[ob + 2 * j]);
            float v1 = fmaf(hi2(acc[j]), inv, B1[ob + 2 * j + 1]);
            gp[j] = make_float2(v0, v1);
        }
    }
}

// ---------------------------------------------------------------------------
#define LSTM3_SMEM_BYTES  ((128*34 + 128*5  + 2*32*34 + 8*3*34) * 8)
#define LSTM32_SMEM_BYTES ((128*34 + 128*34 + 2*32*34 + 2*32*34) * 8)

extern "C" void kernel_launch(void* const* d_in, const int* in_sizes, int n_in,
                              void* d_out, int out_size)
{
    (void)in_sizes; (void)n_in; (void)out_size;
    const float* obs  = (const float*)d_in[0];
    const float* h0t  = (const float*)d_in[1];
    const float* c0t  = (const float*)d_in[2];
    const float* h0g  = (const float*)d_in[3];
    const float* c0g  = (const float*)d_in[4];
    const float* zn   = (const float*)d_in[5];
    const float* WihT = (const float*)d_in[6];
    const float* WhhT = (const float*)d_in[7];
    const float* bihT = (const float*)d_in[8];
    const float* bhhT = (const float*)d_in[9];
    const float* WihG = (const float*)d_in[10];
    const float* WhhG = (const float*)d_in[11];
    const float* bihG = (const float*)d_in[12];
    const float* bhhG = (const float*)d_in[13];
    const float* w0   = (const float*)d_in[14];
    const float* as0  = (const float*)d_in[15];
    const float* ad0  = (const float*)d_in[16];
    const float* b0   = (const float*)d_in[17];
    const float* w1   = (const float*)d_in[18];
    const float* as1  = (const float*)d_in[19];
    const float* ad1  = (const float*)d_in[20];
    const float* b1   = (const float*)d_in[21];

    float* out = (float*)d_out;
    float* enc = out;                                  // [N,72]
    float* ghs = out + (size_t)NTOT * 72;              // [T,N,32]
    float* ths = ghs + (size_t)TT * NTOT * 32;         // [T,N,32]

    float* gin = nullptr;
    cudaGetSymbolAddress((void**)&gin, g_graph_in);

    cudaFuncSetAttribute(lstm_kernel<3, false>,
                         cudaFuncAttributeMaxDynamicSharedMemorySize, LSTM3_SMEM_BYTES);
    cudaFuncSetAttribute(lstm_kernel<32, true>,
                         cudaFuncAttributeMaxDynamicSharedMemorySize, LSTM32_SMEM_BYTES);
    cudaFuncSetAttribute(gat_kernel,
                         cudaFuncAttributeMaxDynamicSharedMemorySize, GAT_SMEM_BYTES);

    // 1) traj LSTM -> traj_hs (directly into output region)
    lstm_kernel<3, false><<<NTOT / 64, 256, LSTM3_SMEM_BYTES>>>(
        obs, h0t, c0t, WihT, WhhT, bihT, bhhT, ths, nullptr, nullptr, nullptr);

    // 2) GAT encoder -> graph_in scratch
    gat_kernel<<<NS * TT, 256, GAT_SMEM_BYTES>>>(
        ths, w0, as0, ad0, b0, w1, as1, ad1, b1, gin);

    // 3) graph LSTM -> graph_hs + encoded (traj_hs[-1] | graph_hs[-1] | noise)
    lstm_kernel<32, true><<<NTOT / 64, 256, LSTM32_SMEM_BYTES>>>(
        gin, h0g, c0g, WihG, WhhG, bihG, bhhG, ghs,
        ths + (size_t)(TT - 1) * NTOT * 32, zn, enc);
}